// round 3
// baseline (speedup 1.0000x reference)
#include <cuda_runtime.h>
#include <cuda_fp16.h>
#include <cstdint>

// ---------------------------------------------------------------------------
// Problem constants
// ---------------------------------------------------------------------------
#define B_BATCH 16
#define N_NODES 256
#define NODE_DIM 512
#define COND_DIM 512
#define EDGE_DIM 128
#define E_TOT 262144
#define LN_EPS 1e-5f

#define M_TILE 128
#define MAIN_TILES (E_TOT / M_TILE)              // 2048
#define G1_TILES ((B_BATCH * N_NODES) / M_TILE)  // 32

// SMEM tiles: [128 rows][256+8 halves] (pad 8 halves = 16B)
#define STRIDE_H 264
#define STRIDE_BYTES (STRIDE_H * 2)     // 528
#define TILE_BYTES (128 * STRIDE_BYTES) // 67584
#define STAGE_STRIDE 132                // floats; 528B rows (aliases A tile)

// SMEM layout (dynamic)
#define OFF_ROWA  0       // int[128]
#define OFF_ROWB  512
#define OFF_GAMMA 1024    // float[128]
#define OFF_BETA  1536
#define OFF_BF    2048
#define OFF_MU    2560
#define OFF_RI    3072
#define OFF_A     3584
#define OFF_B     (OFF_A + TILE_BYTES)           // 71168
#define SMEM_BYTES (OFF_B + TILE_BYTES)          // 138752

// ---------------------------------------------------------------------------
// Device scratch (16B-aligned: accessed via uint4)
// ---------------------------------------------------------------------------
__device__ __align__(16) __half g_wn[EDGE_DIM * NODE_DIM];             // 128KB
__device__ __align__(16) __half g_wfilm[EDGE_DIM * 2 * EDGE_DIM];      // 64KB
__device__ __align__(16) __half g_nodes[B_BATCH * N_NODES * EDGE_DIM]; // 1MB
__device__ float g_gb[B_BATCH * 2 * EDGE_DIM];

// ---------------------------------------------------------------------------
// Helpers
// ---------------------------------------------------------------------------
__device__ __forceinline__ uint32_t smem_to_u32(const void* p) {
    uint32_t a;
    asm("{ .reg .u64 t; cvta.to.shared.u64 t, %1; cvt.u32.u64 %0, t; }"
        : "=r"(a) : "l"(p));
    return a;
}

#define LDSM_X4(r0, r1, r2, r3, addr) \
    asm volatile("ldmatrix.sync.aligned.m8n8.x4.shared.b16 {%0,%1,%2,%3}, [%4];" \
        : "=r"(r0), "=r"(r1), "=r"(r2), "=r"(r3) : "r"(addr))

#define MMA16816(c, a0, a1, a2, a3, b0, b1) \
    asm volatile("mma.sync.aligned.m16n8k16.row.col.f32.f16.f16.f32 " \
        "{%0,%1,%2,%3}, {%4,%5,%6,%7}, {%8,%9}, {%0,%1,%2,%3};" \
        : "+f"((c)[0]), "+f"((c)[1]), "+f"((c)[2]), "+f"((c)[3]) \
        : "r"(a0), "r"(a1), "r"(a2), "r"(a3), "r"(b0), "r"(b1))

__device__ __forceinline__ uint32_t pk2h(float a, float b) {
    __half2 h = __floats2half2_rn(a, b);
    return reinterpret_cast<uint32_t&>(h);
}

// ---------------------------------------------------------------------------
// Prep: weight norms -> fp16 tables; gb = cond FiLM params (fp32 exact)
// ---------------------------------------------------------------------------
__global__ void prep_kernel(const float* __restrict__ v_node, const float* __restrict__ g_node,
                            const float* __restrict__ w_film,
                            const float* __restrict__ v_cond, const float* __restrict__ g_cond,
                            const float* __restrict__ b_cond, const float* __restrict__ cond_feats) {
    __shared__ float red[4];
    int blk = blockIdx.x, tid = threadIdx.x, lane = tid & 31, wid = tid >> 5;

    if (blk < 128) {
        int r = blk;
        float s = 0.f;
        for (int k = tid; k < NODE_DIM; k += 128) { float v = v_node[r * NODE_DIM + k]; s += v * v; }
        #pragma unroll
        for (int o = 16; o; o >>= 1) s += __shfl_xor_sync(0xffffffffu, s, o);
        if (lane == 0) red[wid] = s;
        __syncthreads();
        float scale = g_node[r] * rsqrtf(red[0] + red[1] + red[2] + red[3]);
        for (int k = tid; k < NODE_DIM; k += 128)
            g_wn[r * NODE_DIM + k] = __float2half(v_node[r * NODE_DIM + k] * scale);
    } else if (blk < 256) {
        int r = blk - 128;
        for (int k = tid; k < 2 * EDGE_DIM; k += 128)
            g_wfilm[r * 2 * EDGE_DIM + k] = __float2half(w_film[r * 2 * EDGE_DIM + k]);
    } else {
        int c = blk - 256;
        float s = 0.f;
        for (int k = tid; k < COND_DIM; k += 128) { float v = v_cond[c * COND_DIM + k]; s += v * v; }
        #pragma unroll
        for (int o = 16; o; o >>= 1) s += __shfl_xor_sync(0xffffffffu, s, o);
        if (lane == 0) red[wid] = s;
        __syncthreads();
        float scale = g_cond[c] * rsqrtf(red[0] + red[1] + red[2] + red[3]);
        __syncthreads();
        for (int b = 0; b < B_BATCH; ++b) {
            float p = 0.f;
            for (int k = tid; k < COND_DIM; k += 128)
                p += cond_feats[b * COND_DIM + k] * v_cond[c * COND_DIM + k];
            #pragma unroll
            for (int o = 16; o; o >>= 1) p += __shfl_xor_sync(0xffffffffu, p, o);
            if (lane == 0) red[wid] = p;
            __syncthreads();
            if (tid == 0)
                g_gb[b * 2 * EDGE_DIM + c] = (red[0] + red[1] + red[2] + red[3]) * scale + b_cond[c];
            __syncthreads();
        }
    }
}

// ---------------------------------------------------------------------------
// Warp-tile MMA core: each warp computes 32(M) x 64(N) over K=256 SMEM tiles.
// ---------------------------------------------------------------------------
struct WarpMMA {
    uint32_t aBase[2];
    uint32_t bBase[4];
    float acc[2][8][4];

    __device__ __forceinline__ void init(uint32_t sb, int wid, int lane) {
        int m0 = (wid & 3) * 32;
        int n0 = (wid >> 2) * 64;
        #pragma unroll
        for (int mi = 0; mi < 2; ++mi) {
            int row = m0 + mi * 16 + (lane & 15);
            aBase[mi] = sb + OFF_A + row * STRIDE_BYTES + ((lane >> 4) << 4);
        }
        #pragma unroll
        for (int nb = 0; nb < 4; ++nb) {
            int row = n0 + nb * 16 + ((lane >> 4) << 3) + (lane & 7);
            bBase[nb] = sb + OFF_B + row * STRIDE_BYTES + (((lane >> 3) & 1) << 4);
        }
        #pragma unroll
        for (int mi = 0; mi < 2; ++mi)
            #pragma unroll
            for (int ni = 0; ni < 8; ++ni)
                #pragma unroll
                for (int j = 0; j < 4; ++j) acc[mi][ni][j] = 0.f;
    }

    __device__ __forceinline__ void run_k256() {
        #pragma unroll 4
        for (int kk = 0; kk < 16; ++kk) {
            uint32_t a[2][4];
            #pragma unroll
            for (int mi = 0; mi < 2; ++mi)
                LDSM_X4(a[mi][0], a[mi][1], a[mi][2], a[mi][3], aBase[mi] + kk * 32);
            uint32_t bf[4][4];
            #pragma unroll
            for (int nb = 0; nb < 4; ++nb)
                LDSM_X4(bf[nb][0], bf[nb][1], bf[nb][2], bf[nb][3], bBase[nb] + kk * 32);
            #pragma unroll
            for (int mi = 0; mi < 2; ++mi)
                #pragma unroll
                for (int ni = 0; ni < 8; ++ni)
                    MMA16816(acc[mi][ni], a[mi][0], a[mi][1], a[mi][2], a[mi][3],
                             bf[ni >> 1][(ni & 1) * 2], bf[ni >> 1][(ni & 1) * 2 + 1]);
        }
    }

    __device__ __forceinline__ void to_stage(float* stage, int wid, int lane) {
        int m0 = (wid & 3) * 32;
        int n0 = (wid >> 2) * 64;
        int rbase = m0 + (lane >> 2);
        int cbase = n0 + 2 * (lane & 3);
        #pragma unroll
        for (int mi = 0; mi < 2; ++mi)
            #pragma unroll
            for (int ni = 0; ni < 8; ++ni) {
                float* p0 = stage + (rbase + mi * 16) * STAGE_STRIDE + cbase + ni * 8;
                p0[0] = acc[mi][ni][0];
                p0[1] = acc[mi][ni][1];
                float* p1 = p0 + 8 * STAGE_STRIDE;
                p1[0] = acc[mi][ni][2];
                p1[1] = acc[mi][ni][3];
            }
    }
};

// ---------------------------------------------------------------------------
// GEMM1: nodes = relu(node_feats @ w_n^T + b_node) -> fp16 table
// ---------------------------------------------------------------------------
__global__ void __launch_bounds__(256, 1)
gemm1_kernel(const float* __restrict__ node_feats, const float* __restrict__ b_node) {
    extern __shared__ char smem[];
    uint32_t sb = smem_to_u32(smem);
    int tid = threadIdx.x, wid = tid >> 5, lane = tid & 31;
    int tile = blockIdx.x;
    float* bn_s = (float*)(smem + OFF_BF);
    if (tid < 128) bn_s[tid] = b_node[tid];

    WarpMMA w;
    w.init(sb, wid, lane);

    for (int p = 0; p < 2; ++p) {
        __syncthreads();
        for (int idx = tid; idx < 4096; idx += 256) {
            int r = idx >> 5, cc = idx & 31;
            const float* s = node_feats + (size_t)(tile * M_TILE + r) * NODE_DIM + p * 256 + cc * 8;
            float4 f0 = *(const float4*)s;
            float4 f1 = *(const float4*)(s + 4);
            uint4 u;
            u.x = pk2h(f0.x, f0.y); u.y = pk2h(f0.z, f0.w);
            u.z = pk2h(f1.x, f1.y); u.w = pk2h(f1.z, f1.w);
            *(uint4*)(smem + OFF_A + r * STRIDE_BYTES + cc * 16) = u;
            const uint4 wv = *(const uint4*)(g_wn + r * NODE_DIM + p * 256 + cc * 8);
            *(uint4*)(smem + OFF_B + r * STRIDE_BYTES + cc * 16) = wv;
        }
        __syncthreads();
        w.run_k256();
    }
    __syncthreads();

    float* stage = (float*)(smem + OFF_A);
    w.to_stage(stage, wid, lane);
    __syncthreads();

    for (int idx = tid; idx < 2048; idx += 256) {
        int r = idx >> 4, q = idx & 15;
        const float* s = stage + r * STAGE_STRIDE + q * 8;
        float4 f0 = *(const float4*)s;
        float4 f1 = *(const float4*)(s + 4);
        int c = q * 8;
        uint4 u;
        u.x = pk2h(fmaxf(f0.x + bn_s[c + 0], 0.f), fmaxf(f0.y + bn_s[c + 1], 0.f));
        u.y = pk2h(fmaxf(f0.z + bn_s[c + 2], 0.f), fmaxf(f0.w + bn_s[c + 3], 0.f));
        u.z = pk2h(fmaxf(f1.x + bn_s[c + 4], 0.f), fmaxf(f1.y + bn_s[c + 5], 0.f));
        u.w = pk2h(fmaxf(f1.z + bn_s[c + 6], 0.f), fmaxf(f1.w + bn_s[c + 7], 0.f));
        *(uint4*)(g_nodes + (size_t)(tile * M_TILE + r) * EDGE_DIM + c) = u;
    }
}

// ---------------------------------------------------------------------------
// Main: gather -> MMA (128x128x256) -> LayerNorm + FiLM + ReLU -> out
// eidx is int32 in practice (JAX x64 disabled); sniff for int64 at runtime:
// values < 2^20, so if stored int64 (LE), odd 32-bit words are all zero.
// ---------------------------------------------------------------------------
__global__ void __launch_bounds__(256, 1)
film_kernel(const int* __restrict__ eidx32, const float* __restrict__ b_film,
            float* __restrict__ out) {
    extern __shared__ char smem[];
    uint32_t sb = smem_to_u32(smem);
    int tid = threadIdx.x, wid = tid >> 5, lane = tid & 31;
    int tile = blockIdx.x;

    int* rowA_s = (int*)(smem + OFF_ROWA);
    int* rowB_s = (int*)(smem + OFF_ROWB);
    float* gam_s = (float*)(smem + OFF_GAMMA);
    float* bet_s = (float*)(smem + OFF_BETA);
    float* bf_s  = (float*)(smem + OFF_BF);
    float* mu_s  = (float*)(smem + OFF_MU);
    float* ri_s  = (float*)(smem + OFF_RI);

    if (tid < 128) {
        // dtype sniff (uniform across all threads/blocks; deterministic)
        int stride = (eidx32[1] == 0 && eidx32[3] == 0 && eidx32[5] == 0) ? 2 : 1;
        int ei = eidx32[(size_t)(tile * M_TILE + tid) * stride];
        rowA_s[tid] = ei >> 8;                         // b*256 + i
        rowB_s[tid] = ((ei >> 16) << 8) | (ei & 255);  // b*256 + j
        int batch = tile >> 7;                         // 128 tiles per batch
        gam_s[tid] = g_gb[batch * 2 * EDGE_DIM + tid] + 1.0f;
        bet_s[tid] = g_gb[batch * 2 * EDGE_DIM + EDGE_DIM + tid];
        bf_s[tid]  = b_film[tid];
    }
    __syncthreads();

    for (int idx = tid; idx < 4096; idx += 256) {
        int r = idx >> 5, cc = idx & 31;
        const uint4 wv = *(const uint4*)(g_wfilm + r * 256 + cc * 8);
        *(uint4*)(smem + OFF_B + r * STRIDE_BYTES + cc * 16) = wv;
        int src = (cc < 16) ? rowA_s[r] : rowB_s[r];
        const uint4 av = *(const uint4*)(g_nodes + (size_t)src * EDGE_DIM + (cc & 15) * 8);
        *(uint4*)(smem + OFF_A + r * STRIDE_BYTES + cc * 16) = av;
    }
    __syncthreads();

    WarpMMA w;
    w.init(sb, wid, lane);
    w.run_k256();
    __syncthreads();

    float* stage = (float*)(smem + OFF_A);
    w.to_stage(stage, wid, lane);
    __syncthreads();

    if (tid < 128) {
        const float* srow = stage + tid * STAGE_STRIDE;
        float sum = 0.f, sq = 0.f;
        #pragma unroll
        for (int c = 0; c < 128; c += 4) {
            float4 v = *(const float4*)(srow + c);
            float x0 = v.x + bf_s[c + 0];
            float x1 = v.y + bf_s[c + 1];
            float x2 = v.z + bf_s[c + 2];
            float x3 = v.w + bf_s[c + 3];
            sum += x0 + x1 + x2 + x3;
            sq += x0 * x0 + x1 * x1 + x2 * x2 + x3 * x3;
        }
        float mu = sum * (1.f / 128.f);
        float var = sq * (1.f / 128.f) - mu * mu;
        mu_s[tid] = mu;
        ri_s[tid] = rsqrtf(fmaxf(var, 0.f) + LN_EPS);
    }
    __syncthreads();

    for (int idx = tid; idx < 4096; idx += 256) {
        int r = idx >> 5, q = idx & 31;
        float mu = mu_s[r], ri = ri_s[r];
        const float* s = stage + r * STAGE_STRIDE + q * 4;
        float4 v = *(const float4*)s;
        int c = q * 4;
        float4 o;
        o.x = fmaxf((v.x + bf_s[c + 0] - mu) * ri * gam_s[c + 0] + bet_s[c + 0], 0.f);
        o.y = fmaxf((v.y + bf_s[c + 1] - mu) * ri * gam_s[c + 1] + bet_s[c + 1], 0.f);
        o.z = fmaxf((v.z + bf_s[c + 2] - mu) * ri * gam_s[c + 2] + bet_s[c + 2], 0.f);
        o.w = fmaxf((v.w + bf_s[c + 3] - mu) * ri * gam_s[c + 3] + bet_s[c + 3], 0.f);
        *(float4*)(out + (size_t)(tile * M_TILE + r) * EDGE_DIM + c) = o;
    }
}

// ---------------------------------------------------------------------------
// Launch
// ---------------------------------------------------------------------------
extern "C" void kernel_launch(void* const* d_in, const int* in_sizes, int n_in,
                              void* d_out, int out_size) {
    const float* node_feats = (const float*)d_in[0];
    const float* cond_feats = (const float*)d_in[1];
    const int*   eidx       = (const int*)d_in[2];
    const float* v_node     = (const float*)d_in[3];
    const float* g_node     = (const float*)d_in[4];
    const float* b_node     = (const float*)d_in[5];
    const float* v_cond     = (const float*)d_in[6];
    const float* g_cond     = (const float*)d_in[7];
    const float* b_cond     = (const float*)d_in[8];
    const float* w_film     = (const float*)d_in[9];
    const float* b_film     = (const float*)d_in[10];
    float* out = (float*)d_out;

    cudaFuncSetAttribute(gemm1_kernel, cudaFuncAttributeMaxDynamicSharedMemorySize, SMEM_BYTES);
    cudaFuncSetAttribute(film_kernel,  cudaFuncAttributeMaxDynamicSharedMemorySize, SMEM_BYTES);

    prep_kernel<<<512, 128>>>(v_node, g_node, w_film, v_cond, g_cond, b_cond, cond_feats);
    gemm1_kernel<<<G1_TILES, 256, SMEM_BYTES>>>(node_feats, b_node);
    film_kernel<<<MAIN_TILES, 256, SMEM_BYTES>>>(eidx, b_film, out);
}

// round 5
// speedup vs baseline: 1.7780x; 1.7780x over previous
#include <cuda_runtime.h>
#include <cuda_fp16.h>
#include <cstdint>

// ---------------------------------------------------------------------------
// Problem constants
// ---------------------------------------------------------------------------
#define B_BATCH 16
#define N_NODES 256
#define NODE_DIM 512
#define COND_DIM 512
#define EDGE_DIM 128
#define E_TOT 262144
#define LN_EPS 1e-5f

#define M_TILE 128
#define MAIN_TILES (E_TOT / M_TILE)              // 2048
#define FILM_CTAS 148                            // one persistent wave on GB300
#define G1_TILES ((B_BATCH * N_NODES) / M_TILE)  // 32

// SMEM A/B tiles: [128 rows][256+8 halves] (16B row pad)
#define STRIDE_H 264
#define STRIDE_BYTES (STRIDE_H * 2)     // 528
#define TILE_BYTES (128 * STRIDE_BYTES) // 67584
#define STAGE_STRIDE 132                // floats (gemm1 only)

// --- film kernel SMEM layout ---
#define OFF_SUM 0         // float[256]  (two N-halves x 128 rows)
#define OFF_SQ  1024      // float[256]
#define OFF_GAM 2048      // float[128]
#define OFF_BET 2560
#define OFF_BF  3072
#define OFF_FB  3584                      // w_film tile
#define OFF_FA0 (OFF_FB + TILE_BYTES)     // 71168
#define OFF_FA1 (OFF_FA0 + TILE_BYTES)    // 138752
#define SMEM_F  (OFF_FA1 + TILE_BYTES)    // 206336

// --- gemm1 kernel SMEM layout ---
#define G1_BF   2048
#define G1_A    3584
#define G1_B    (G1_A + TILE_BYTES)
#define SMEM_G  (G1_B + TILE_BYTES)       // 138752

// ---------------------------------------------------------------------------
// Device scratch (16B-aligned)
// ---------------------------------------------------------------------------
__device__ __align__(16) __half g_wn[EDGE_DIM * NODE_DIM];             // 128KB
__device__ __align__(16) __half g_wfilm[EDGE_DIM * 2 * EDGE_DIM];      // 64KB
__device__ __align__(16) __half g_nodes[B_BATCH * N_NODES * EDGE_DIM]; // 1MB
__device__ float g_gb[B_BATCH * 2 * EDGE_DIM];

// ---------------------------------------------------------------------------
// Helpers
// ---------------------------------------------------------------------------
__device__ __forceinline__ uint32_t smem_to_u32(const void* p) {
    uint32_t a;
    asm("{ .reg .u64 t; cvta.to.shared.u64 t, %1; cvt.u32.u64 %0, t; }"
        : "=r"(a) : "l"(p));
    return a;
}

#define LDSM_X4(r0, r1, r2, r3, addr) \
    asm volatile("ldmatrix.sync.aligned.m8n8.x4.shared.b16 {%0,%1,%2,%3}, [%4];" \
        : "=r"(r0), "=r"(r1), "=r"(r2), "=r"(r3) : "r"(addr))

#define MMA16816(c, a0, a1, a2, a3, b0, b1) \
    asm volatile("mma.sync.aligned.m16n8k16.row.col.f32.f16.f16.f32 " \
        "{%0,%1,%2,%3}, {%4,%5,%6,%7}, {%8,%9}, {%0,%1,%2,%3};" \
        : "+f"((c)[0]), "+f"((c)[1]), "+f"((c)[2]), "+f"((c)[3]) \
        : "r"(a0), "r"(a1), "r"(a2), "r"(a3), "r"(b0), "r"(b1))

__device__ __forceinline__ void cp_async16(uint32_t dst, const void* src) {
    asm volatile("cp.async.cg.shared.global [%0], [%1], 16;" :: "r"(dst), "l"(src));
}
#define CP_COMMIT() asm volatile("cp.async.commit_group;" ::: "memory")
#define CP_WAIT(n)  asm volatile("cp.async.wait_group %0;" :: "n"(n) : "memory")

__device__ __forceinline__ uint32_t pk2h(float a, float b) {
    __half2 h = __floats2half2_rn(a, b);
    return reinterpret_cast<uint32_t&>(h);
}

__device__ __forceinline__ float warp_red(float v) {
    #pragma unroll
    for (int o = 16; o; o >>= 1) v += __shfl_xor_sync(0xffffffffu, v, o);
    return v;
}

// ---------------------------------------------------------------------------
// Prep: weight norms -> fp16 tables; gb = cond FiLM params (fp32 exact)
// ---------------------------------------------------------------------------
__global__ void prep_kernel(const float* __restrict__ v_node, const float* __restrict__ g_node,
                            const float* __restrict__ w_film,
                            const float* __restrict__ v_cond, const float* __restrict__ g_cond,
                            const float* __restrict__ b_cond, const float* __restrict__ cond_feats) {
    int blk = blockIdx.x, tid = threadIdx.x, lane = tid & 31, wid = tid >> 5;

    if (blk < 128) {
        __shared__ float red[4];
        int r = blk;
        float s = 0.f;
        for (int k = tid; k < NODE_DIM; k += 128) { float v = v_node[r * NODE_DIM + k]; s += v * v; }
        s = warp_red(s);
        if (lane == 0) red[wid] = s;
        __syncthreads();
        float scale = g_node[r] * rsqrtf(red[0] + red[1] + red[2] + red[3]);
        for (int k = tid; k < NODE_DIM; k += 128)
            g_wn[r * NODE_DIM + k] = __float2half(v_node[r * NODE_DIM + k] * scale);
    } else if (blk < 256) {
        int r = blk - 128;
        for (int k = tid; k < 2 * EDGE_DIM; k += 128)
            g_wfilm[r * 2 * EDGE_DIM + k] = __float2half(w_film[r * 2 * EDGE_DIM + k]);
    } else {
        // gb[b][c]: warp-parallel over batches, no block syncs
        int c = blk - 256;
        const float* vrow = v_cond + (size_t)c * COND_DIM;
        float s = 0.f;
        for (int k = lane; k < COND_DIM; k += 32) { float v = vrow[k]; s += v * v; }
        s = warp_red(s);
        float scale = g_cond[c] * rsqrtf(__shfl_sync(0xffffffffu, s, 0));
        float bc = b_cond[c];
        for (int b = wid; b < B_BATCH; b += 4) {
            float p = 0.f;
            const float* crow = cond_feats + (size_t)b * COND_DIM;
            for (int k = lane; k < COND_DIM; k += 32) p += crow[k] * vrow[k];
            p = warp_red(p);
            if (lane == 0) g_gb[b * 2 * EDGE_DIM + c] = p * scale + bc;
        }
    }
}

// ---------------------------------------------------------------------------
// Warp-tile MMA core: warp computes 32(M) x 64(N) over a K=256 SMEM tile pair
// ---------------------------------------------------------------------------
struct WarpMMA {
    uint32_t aBase[2];
    uint32_t bBase[4];
    float acc[2][8][4];

    __device__ __forceinline__ void init(uint32_t sb, uint32_t aOff, uint32_t bOff,
                                         int wid, int lane) {
        int m0 = (wid & 3) * 32;
        int n0 = (wid >> 2) * 64;
        #pragma unroll
        for (int mi = 0; mi < 2; ++mi) {
            int row = m0 + mi * 16 + (lane & 15);
            aBase[mi] = sb + aOff + row * STRIDE_BYTES + ((lane >> 4) << 4);
        }
        #pragma unroll
        for (int nb = 0; nb < 4; ++nb) {
            int row = n0 + nb * 16 + ((lane >> 4) << 3) + (lane & 7);
            bBase[nb] = sb + bOff + row * STRIDE_BYTES + (((lane >> 3) & 1) << 4);
        }
    }

    __device__ __forceinline__ void zero() {
        #pragma unroll
        for (int mi = 0; mi < 2; ++mi)
            #pragma unroll
            for (int ni = 0; ni < 8; ++ni)
                #pragma unroll
                for (int j = 0; j < 4; ++j) acc[mi][ni][j] = 0.f;
    }

    __device__ __forceinline__ void run_k256(uint32_t aDelta) {
        #pragma unroll 4
        for (int kk = 0; kk < 16; ++kk) {
            uint32_t a[2][4];
            #pragma unroll
            for (int mi = 0; mi < 2; ++mi)
                LDSM_X4(a[mi][0], a[mi][1], a[mi][2], a[mi][3], aBase[mi] + aDelta + kk * 32);
            uint32_t bf[4][4];
            #pragma unroll
            for (int nb = 0; nb < 4; ++nb)
                LDSM_X4(bf[nb][0], bf[nb][1], bf[nb][2], bf[nb][3], bBase[nb] + kk * 32);
            #pragma unroll
            for (int mi = 0; mi < 2; ++mi)
                #pragma unroll
                for (int ni = 0; ni < 8; ++ni)
                    MMA16816(acc[mi][ni], a[mi][0], a[mi][1], a[mi][2], a[mi][3],
                             bf[ni >> 1][(ni & 1) * 2], bf[ni >> 1][(ni & 1) * 2 + 1]);
        }
    }

    __device__ __forceinline__ void to_stage(float* stage, int wid, int lane) {
        int m0 = (wid & 3) * 32;
        int n0 = (wid >> 2) * 64;
        int rbase = m0 + (lane >> 2);
        int cbase = n0 + 2 * (lane & 3);
        #pragma unroll
        for (int mi = 0; mi < 2; ++mi)
            #pragma unroll
            for (int ni = 0; ni < 8; ++ni) {
                float* p0 = stage + (rbase + mi * 16) * STAGE_STRIDE + cbase + ni * 8;
                p0[0] = acc[mi][ni][0];
                p0[1] = acc[mi][ni][1];
                float* p1 = p0 + 8 * STAGE_STRIDE;
                p1[0] = acc[mi][ni][2];
                p1[1] = acc[mi][ni][3];
            }
    }
};

// ---------------------------------------------------------------------------
// GEMM1: nodes = relu(node_feats @ w_n^T + b_node) -> fp16 table
// ---------------------------------------------------------------------------
__global__ void __launch_bounds__(256, 1)
gemm1_kernel(const float* __restrict__ node_feats, const float* __restrict__ b_node) {
    extern __shared__ char smem[];
    uint32_t sb = smem_to_u32(smem);
    int tid = threadIdx.x, wid = tid >> 5, lane = tid & 31;
    int tile = blockIdx.x;
    float* bn_s = (float*)(smem + G1_BF);
    if (tid < 128) bn_s[tid] = b_node[tid];

    WarpMMA w;
    w.init(sb, G1_A, G1_B, wid, lane);
    w.zero();

    for (int p = 0; p < 2; ++p) {
        __syncthreads();
        for (int idx = tid; idx < 4096; idx += 256) {
            int r = idx >> 5, cc = idx & 31;
            const float* s = node_feats + (size_t)(tile * M_TILE + r) * NODE_DIM + p * 256 + cc * 8;
            float4 f0 = *(const float4*)s;
            float4 f1 = *(const float4*)(s + 4);
            uint4 u;
            u.x = pk2h(f0.x, f0.y); u.y = pk2h(f0.z, f0.w);
            u.z = pk2h(f1.x, f1.y); u.w = pk2h(f1.z, f1.w);
            *(uint4*)(smem + G1_A + r * STRIDE_BYTES + cc * 16) = u;
            const uint4 wv = *(const uint4*)(g_wn + r * NODE_DIM + p * 256 + cc * 8);
            *(uint4*)(smem + G1_B + r * STRIDE_BYTES + cc * 16) = wv;
        }
        __syncthreads();
        w.run_k256(0);
    }
    __syncthreads();

    float* stage = (float*)(smem + G1_A);
    w.to_stage(stage, wid, lane);
    __syncthreads();

    for (int idx = tid; idx < 2048; idx += 256) {
        int r = idx >> 4, q = idx & 15;
        const float* s = stage + r * STAGE_STRIDE + q * 8;
        float4 f0 = *(const float4*)s;
        float4 f1 = *(const float4*)(s + 4);
        int c = q * 8;
        uint4 u;
        u.x = pk2h(fmaxf(f0.x + bn_s[c + 0], 0.f), fmaxf(f0.y + bn_s[c + 1], 0.f));
        u.y = pk2h(fmaxf(f0.z + bn_s[c + 2], 0.f), fmaxf(f0.w + bn_s[c + 3], 0.f));
        u.z = pk2h(fmaxf(f1.x + bn_s[c + 4], 0.f), fmaxf(f1.y + bn_s[c + 5], 0.f));
        u.w = pk2h(fmaxf(f1.z + bn_s[c + 6], 0.f), fmaxf(f1.w + bn_s[c + 7], 0.f));
        *(uint4*)(g_nodes + (size_t)(tile * M_TILE + r) * EDGE_DIM + c) = u;
    }
}

// ---------------------------------------------------------------------------
// film: persistent CTAs (strided tiles), cp.async double-buffer, direct epilogue
// ---------------------------------------------------------------------------
__device__ __forceinline__ void issue_gather(uint32_t dst_base, const int* __restrict__ eidx32,
                                             int stride, int gtile, int tid) {
    int cc = tid & 31;
    bool hiHalf = cc >= 16;
    const __half* src_col = g_nodes + (cc & 15) * 8;
    #pragma unroll
    for (int k = 0; k < 16; ++k) {
        int r = (tid >> 5) + 8 * k;
        int ei = eidx32[(size_t)(gtile * M_TILE + r) * stride];
        int src = hiHalf ? (((ei >> 16) << 8) | (ei & 255)) : (ei >> 8);
        cp_async16(dst_base + r * STRIDE_BYTES + cc * 16, src_col + (size_t)src * EDGE_DIM);
    }
}

__global__ void __launch_bounds__(256, 1)
film_kernel(const int* __restrict__ eidx32, const float* __restrict__ b_film,
            float* __restrict__ out) {
    extern __shared__ char smem[];
    uint32_t sb = smem_to_u32(smem);
    int tid = threadIdx.x, wid = tid >> 5, lane = tid & 31;
    int cta = blockIdx.x;
    int my_tiles = (MAIN_TILES - cta + FILM_CTAS - 1) / FILM_CTAS;  // 14 or 13

    float* sum_s = (float*)(smem + OFF_SUM);
    float* sq_s  = (float*)(smem + OFF_SQ);
    float* gam_s = (float*)(smem + OFF_GAM);
    float* bet_s = (float*)(smem + OFF_BET);
    float* bf_s  = (float*)(smem + OFF_BF);

    if (tid < 128) bf_s[tid] = b_film[tid];
    // dtype sniff: int64 (LE) => odd words zero (values < 2^20)
    int stride = (eidx32[1] == 0 && eidx32[3] == 0 && eidx32[5] == 0) ? 2 : 1;

    // B (w_film) once per CTA + first A tile, one cp.async group
    {
        int cc = tid & 31;
        #pragma unroll
        for (int k = 0; k < 16; ++k) {
            int r = (tid >> 5) + 8 * k;
            cp_async16(sb + OFF_FB + r * STRIDE_BYTES + cc * 16, g_wfilm + r * 256 + cc * 8);
        }
    }
    issue_gather(sb + OFF_FA0, eidx32, stride, cta, tid);
    CP_COMMIT();

    WarpMMA w;
    w.init(sb, OFF_FA0, OFF_FB, wid, lane);
    const int m0 = (wid & 3) * 32;
    const int n0 = (wid >> 2) * 64;
    const int halfN = wid >> 2;

    for (int t = 0; t < my_tiles; ++t) {
        int tile = cta + t * FILM_CTAS;
        if (t + 1 < my_tiles) {
            issue_gather(sb + (((t + 1) & 1) ? OFF_FA1 : OFF_FA0), eidx32, stride,
                         tile + FILM_CTAS, tid);
            CP_COMMIT();
            CP_WAIT(1);
        } else {
            CP_WAIT(0);
        }
        __syncthreads();   // tile t resident; orders prev epilogue reads before new writes

        // per-tile gamma/beta (batch = tile >> 7); consumed after the post-stats sync
        if (tid < 128) {
            int batch = tile >> 7;
            gam_s[tid] = g_gb[batch * 2 * EDGE_DIM + tid] + 1.0f;
            bet_s[tid] = g_gb[batch * 2 * EDGE_DIM + EDGE_DIM + tid];
        }

        w.zero();
        w.run_k256((t & 1) ? (uint32_t)(OFF_FA1 - OFF_FA0) : 0u);

        // ---- epilogue: bias + LN stats (quad shuffle + cross-warp smem) ----
        float ps[2][2], pq[2][2];
        #pragma unroll
        for (int mi = 0; mi < 2; ++mi) {
            ps[mi][0] = ps[mi][1] = pq[mi][0] = pq[mi][1] = 0.f;
            #pragma unroll
            for (int ni = 0; ni < 8; ++ni) {
                int c0 = n0 + ni * 8 + 2 * (lane & 3);
                float b0 = bf_s[c0], b1 = bf_s[c0 + 1];
                float x0 = w.acc[mi][ni][0] + b0;
                float x1 = w.acc[mi][ni][1] + b1;
                float x2 = w.acc[mi][ni][2] + b0;
                float x3 = w.acc[mi][ni][3] + b1;
                w.acc[mi][ni][0] = x0; w.acc[mi][ni][1] = x1;
                w.acc[mi][ni][2] = x2; w.acc[mi][ni][3] = x3;
                ps[mi][0] += x0 + x1; pq[mi][0] += x0 * x0 + x1 * x1;
                ps[mi][1] += x2 + x3; pq[mi][1] += x2 * x2 + x3 * x3;
            }
        }
        #pragma unroll
        for (int mi = 0; mi < 2; ++mi)
            #pragma unroll
            for (int h = 0; h < 2; ++h) {
                float s = ps[mi][h], q = pq[mi][h];
                s += __shfl_xor_sync(0xffffffffu, s, 1);
                s += __shfl_xor_sync(0xffffffffu, s, 2);
                q += __shfl_xor_sync(0xffffffffu, q, 1);
                q += __shfl_xor_sync(0xffffffffu, q, 2);
                if ((lane & 3) == 0) {
                    int r = m0 + mi * 16 + h * 8 + (lane >> 2);
                    sum_s[halfN * 128 + r] = s;
                    sq_s[halfN * 128 + r] = q;
                }
            }
        __syncthreads();

        // ---- normalize + FiLM + ReLU, direct float2 stores ----
        size_t rowBase = (size_t)tile * M_TILE;
        #pragma unroll
        for (int mi = 0; mi < 2; ++mi)
            #pragma unroll
            for (int h = 0; h < 2; ++h) {
                int r = m0 + mi * 16 + h * 8 + (lane >> 2);
                float mu = (sum_s[r] + sum_s[128 + r]) * (1.f / 128.f);
                float var = (sq_s[r] + sq_s[128 + r]) * (1.f / 128.f) - mu * mu;
                float ri = rsqrtf(fmaxf(var, 0.f) + LN_EPS);
                float* orow = out + (rowBase + r) * EDGE_DIM;
                #pragma unroll
                for (int ni = 0; ni < 8; ++ni) {
                    int c0 = n0 + ni * 8 + 2 * (lane & 3);
                    float2 o;
                    o.x = fmaxf((w.acc[mi][ni][h * 2 + 0] - mu) * ri * gam_s[c0] + bet_s[c0], 0.f);
                    o.y = fmaxf((w.acc[mi][ni][h * 2 + 1] - mu) * ri * gam_s[c0 + 1] + bet_s[c0 + 1], 0.f);
                    *(float2*)(orow + c0) = o;
                }
            }
        // next iteration's pre-MMA __syncthreads orders these smem reads
        // against the next tile's writes
    }
}

// ---------------------------------------------------------------------------
// Launch
// ---------------------------------------------------------------------------
extern "C" void kernel_launch(void* const* d_in, const int* in_sizes, int n_in,
                              void* d_out, int out_size) {
    const float* node_feats = (const float*)d_in[0];
    const float* cond_feats = (const float*)d_in[1];
    const int*   eidx       = (const int*)d_in[2];
    const float* v_node     = (const float*)d_in[3];
    const float* g_node     = (const float*)d_in[4];
    const float* b_node     = (const float*)d_in[5];
    const float* v_cond     = (const float*)d_in[6];
    const float* g_cond     = (const float*)d_in[7];
    const float* b_cond     = (const float*)d_in[8];
    const float* w_film     = (const float*)d_in[9];
    const float* b_film     = (const float*)d_in[10];
    float* out = (float*)d_out;

    cudaFuncSetAttribute(gemm1_kernel, cudaFuncAttributeMaxDynamicSharedMemorySize, SMEM_G);
    cudaFuncSetAttribute(film_kernel,  cudaFuncAttributeMaxDynamicSharedMemorySize, SMEM_F);

    prep_kernel<<<512, 128>>>(v_node, g_node, w_film, v_cond, g_cond, b_cond, cond_feats);
    gemm1_kernel<<<G1_TILES, 256, SMEM_G>>>(node_feats, b_node);
    film_kernel<<<FILM_CTAS, 256, SMEM_F>>>(eidx, b_film, out);
}

// round 7
// speedup vs baseline: 3.6125x; 2.0318x over previous
#include <cuda_runtime.h>
#include <cuda_fp16.h>
#include <cstdint>

// ---------------------------------------------------------------------------
// Problem constants
// ---------------------------------------------------------------------------
#define B_BATCH 16
#define N_NODES 256
#define NODE_DIM 512
#define COND_DIM 512
#define EDGE_DIM 128
#define E_TOT 262144
#define LN_EPS 1e-5f

#define NROWS (B_BATCH * N_NODES)   // 4096
#define M_G 64
#define G_TILES (NROWS / M_G)       // 64
#define FILM_TILES (E_TOT / 128)    // 2048

// Fused-gemm SMEM layout
// region0: phase1 A-tile 64x(256+8)h stride 528B (33792B) / phase2 nodes 64x(128+8)h stride 272B
// region1: phase1 B-tile 128x528 (67584B) / phase2 wcat 256x272 (69632B)
#define GS_BN 0
#define GS_R0 1024
#define GS_R1 (GS_R0 + 64 * 528)          // 34816
#define SMEM_GEMM (GS_R1 + 256 * 272)     // 104448

// ---------------------------------------------------------------------------
// Device scratch (static, no allocation)
// ---------------------------------------------------------------------------
__device__ __align__(16) __half g_wn[EDGE_DIM * NODE_DIM];        // 128KB
__device__ __align__(16) __half g_wcat[2 * EDGE_DIM * EDGE_DIM];  // 64KB, row c<128: W1 row; row 128+c: W2 row
__device__ float g_gb[B_BATCH * 2 * EDGE_DIM];                    // 16KB
__device__ __align__(16) float g_P[NROWS * 2 * EDGE_DIM];         // 4MB: P[r][0:128]=nodes@W1^T, [128:256]=nodes@W2^T

// ---------------------------------------------------------------------------
// Helpers
// ---------------------------------------------------------------------------
__device__ __forceinline__ uint32_t smem_to_u32(const void* p) {
    uint32_t a;
    asm("{ .reg .u64 t; cvta.to.shared.u64 t, %1; cvt.u32.u64 %0, t; }"
        : "=r"(a) : "l"(p));
    return a;
}

#define LDSM_X4(r0, r1, r2, r3, addr) \
    asm volatile("ldmatrix.sync.aligned.m8n8.x4.shared.b16 {%0,%1,%2,%3}, [%4];" \
        : "=r"(r0), "=r"(r1), "=r"(r2), "=r"(r3) : "r"(addr))

#define MMA16816(c, a0, a1, a2, a3, b0, b1) \
    asm volatile("mma.sync.aligned.m16n8k16.row.col.f32.f16.f16.f32 " \
        "{%0,%1,%2,%3}, {%4,%5,%6,%7}, {%8,%9}, {%0,%1,%2,%3};" \
        : "+f"((c)[0]), "+f"((c)[1]), "+f"((c)[2]), "+f"((c)[3]) \
        : "r"(a0), "r"(a1), "r"(a2), "r"(a3), "r"(b0), "r"(b1))

__device__ __forceinline__ uint32_t pk2h(float a, float b) {
    __half2 h = __floats2half2_rn(a, b);
    return reinterpret_cast<uint32_t&>(h);
}

__device__ __forceinline__ float warp_red(float v) {
    #pragma unroll
    for (int o = 16; o; o >>= 1) v += __shfl_xor_sync(0xffffffffu, v, o);
    return v;
}

// ---------------------------------------------------------------------------
// Prep: g_wn (weight-normed, fp16), g_wcat (reordered w_film fp16), g_gb
// grid 384 x 128
// ---------------------------------------------------------------------------
__global__ void prep_kernel(const float* __restrict__ v_node, const float* __restrict__ g_node,
                            const float* __restrict__ w_film,
                            const float* __restrict__ v_cond, const float* __restrict__ g_cond,
                            const float* __restrict__ b_cond, const float* __restrict__ cond_feats) {
    __shared__ float red[4];
    int blk = blockIdx.x, tid = threadIdx.x, lane = tid & 31, wid = tid >> 5;

    if (blk < 128) {
        int r = blk;
        float4 v4 = *(const float4*)(v_node + (size_t)r * NODE_DIM + tid * 4);
        float s = v4.x * v4.x + v4.y * v4.y + v4.z * v4.z + v4.w * v4.w;
        s = warp_red(s);
        if (lane == 0) red[wid] = s;
        __syncthreads();
        float scale = g_node[r] * rsqrtf(red[0] + red[1] + red[2] + red[3]);
        uint2 u;
        u.x = pk2h(v4.x * scale, v4.y * scale);
        u.y = pk2h(v4.z * scale, v4.w * scale);
        *(uint2*)(g_wn + (size_t)r * NODE_DIM + tid * 4) = u;
        // reorder w_film row r into wcat rows r (k<128) and 128+r (k>=128)
        float2 wf = *(const float2*)(w_film + (size_t)r * 256 + tid * 2);
        uint32_t h = pk2h(wf.x, wf.y);
        if (tid < 64)
            *(uint32_t*)(g_wcat + (size_t)r * 128 + tid * 2) = h;
        else
            *(uint32_t*)(g_wcat + (size_t)(128 + r) * 128 + tid * 2 - 128) = h;
    } else {
        int c = blk - 128;  // 0..255
        const float* vrow = v_cond + (size_t)c * COND_DIM;
        float4 v4 = *(const float4*)(vrow + tid * 4);
        float s = v4.x * v4.x + v4.y * v4.y + v4.z * v4.z + v4.w * v4.w;
        s = warp_red(s);
        if (lane == 0) red[wid] = s;
        __syncthreads();
        float scale = g_cond[c] * rsqrtf(red[0] + red[1] + red[2] + red[3]);
        float bc = b_cond[c];
        #pragma unroll
        for (int bb = 0; bb < 4; ++bb) {
            int b = wid * 4 + bb;
            const float* crow = cond_feats + (size_t)b * COND_DIM;
            float p = 0.f;
            #pragma unroll
            for (int t = 0; t < 4; ++t) {
                int k4 = (lane + t * 32) * 4;
                float4 cf = *(const float4*)(crow + k4);
                float4 vv = *(const float4*)(vrow + k4);
                p += cf.x * vv.x + cf.y * vv.y + cf.z * vv.z + cf.w * vv.w;
            }
            p = warp_red(p);
            if (lane == 0) g_gb[b * 2 * EDGE_DIM + c] = p * scale + bc;
        }
    }
}

// ---------------------------------------------------------------------------
// Fused GEMM: nodes tile = relu(node_feats @ w_n^T + b_node)  [64x128, fp16 smem]
//             P tile     = nodes tile @ w_cat^T               [64x256, fp32 -> g_P]
// grid 64 x 256
// ---------------------------------------------------------------------------
__global__ void __launch_bounds__(256, 1)
gemm_kernel(const float* __restrict__ node_feats, const float* __restrict__ b_node) {
    extern __shared__ char smem[];
    uint32_t sb = smem_to_u32(smem);
    int tid = threadIdx.x, wid = tid >> 5, lane = tid & 31;
    int tile = blockIdx.x;
    float* bn_s = (float*)(smem + GS_BN);
    if (tid < 128) bn_s[tid] = b_node[tid];

    // ---- phase 1: 64x128x512 (two K=256 passes) ----
    const int m0 = (wid & 1) * 32;
    const int n1 = (wid >> 1) * 32;   // phase-1 N offset
    uint32_t aB1[2], bB1[2];
    #pragma unroll
    for (int mi = 0; mi < 2; ++mi)
        aB1[mi] = sb + GS_R0 + (m0 + mi * 16 + (lane & 15)) * 528 + ((lane >> 4) << 4);
    #pragma unroll
    for (int nb = 0; nb < 2; ++nb)
        bB1[nb] = sb + GS_R1 + (n1 + nb * 16 + ((lane >> 4) << 3) + (lane & 7)) * 528
                  + (((lane >> 3) & 1) << 4);

    float acc1[2][4][4];
    #pragma unroll
    for (int mi = 0; mi < 2; ++mi)
        #pragma unroll
        for (int ni = 0; ni < 4; ++ni)
            #pragma unroll
            for (int j = 0; j < 4; ++j) acc1[mi][ni][j] = 0.f;

    for (int p = 0; p < 2; ++p) {
        __syncthreads();
        // A: node_feats rows tile*64 .. +63, fp32 -> fp16
        for (int idx = tid; idx < 2048; idx += 256) {
            int r = idx >> 5, cc = idx & 31;
            const float* s = node_feats + (size_t)(tile * M_G + r) * NODE_DIM + p * 256 + cc * 8;
            float4 f0 = *(const float4*)s;
            float4 f1 = *(const float4*)(s + 4);
            uint4 u;
            u.x = pk2h(f0.x, f0.y); u.y = pk2h(f0.z, f0.w);
            u.z = pk2h(f1.x, f1.y); u.w = pk2h(f1.z, f1.w);
            *(uint4*)(smem + GS_R0 + r * 528 + cc * 16) = u;
        }
        // B: g_wn rows 0..127
        for (int idx = tid; idx < 4096; idx += 256) {
            int r = idx >> 5, cc = idx & 31;
            const uint4 wv = *(const uint4*)(g_wn + (size_t)r * NODE_DIM + p * 256 + cc * 8);
            *(uint4*)(smem + GS_R1 + r * 528 + cc * 16) = wv;
        }
        __syncthreads();
        #pragma unroll 4
        for (int kk = 0; kk < 16; ++kk) {
            uint32_t a[2][4], bf[2][4];
            #pragma unroll
            for (int mi = 0; mi < 2; ++mi)
                LDSM_X4(a[mi][0], a[mi][1], a[mi][2], a[mi][3], aB1[mi] + kk * 32);
            #pragma unroll
            for (int nb = 0; nb < 2; ++nb)
                LDSM_X4(bf[nb][0], bf[nb][1], bf[nb][2], bf[nb][3], bB1[nb] + kk * 32);
            #pragma unroll
            for (int mi = 0; mi < 2; ++mi)
                #pragma unroll
                for (int ni = 0; ni < 4; ++ni)
                    MMA16816(acc1[mi][ni], a[mi][0], a[mi][1], a[mi][2], a[mi][3],
                             bf[ni >> 1][(ni & 1) * 2], bf[ni >> 1][(ni & 1) * 2 + 1]);
        }
    }
    __syncthreads();  // all phase-1 LDSM reads done; regions reusable

    // ---- store nodes (relu+bias, fp16) into region0; fill wcat into region1 ----
    {
        int rb = m0 + (lane >> 2);
        int cb = n1 + 2 * (lane & 3);
        #pragma unroll
        for (int mi = 0; mi < 2; ++mi)
            #pragma unroll
            for (int ni = 0; ni < 4; ++ni) {
                int r = rb + mi * 16;
                int c = cb + ni * 8;
                float b0 = bn_s[c], b1 = bn_s[c + 1];
                *(uint32_t*)(smem + GS_R0 + r * 272 + c * 2) =
                    pk2h(fmaxf(acc1[mi][ni][0] + b0, 0.f), fmaxf(acc1[mi][ni][1] + b1, 0.f));
                *(uint32_t*)(smem + GS_R0 + (r + 8) * 272 + c * 2) =
                    pk2h(fmaxf(acc1[mi][ni][2] + b0, 0.f), fmaxf(acc1[mi][ni][3] + b1, 0.f));
            }
    }
    for (int idx = tid; idx < 4096; idx += 256) {
        int r = idx >> 4, cc = idx & 15;
        const uint4 wv = *(const uint4*)(g_wcat + (size_t)r * 128 + cc * 8);
        *(uint4*)(smem + GS_R1 + r * 272 + cc * 16) = wv;
    }
    __syncthreads();

    // ---- phase 2: 64x256x128 ----
    const int n2 = (wid >> 1) * 64;
    uint32_t aB2[2], bB2[4];
    #pragma unroll
    for (int mi = 0; mi < 2; ++mi)
        aB2[mi] = sb + GS_R0 + (m0 + mi * 16 + (lane & 15)) * 272 + ((lane >> 4) << 4);
    #pragma unroll
    for (int nb = 0; nb < 4; ++nb)
        bB2[nb] = sb + GS_R1 + (n2 + nb * 16 + ((lane >> 4) << 3) + (lane & 7)) * 272
                  + (((lane >> 3) & 1) << 4);

    float acc2[2][8][4];
    #pragma unroll
    for (int mi = 0; mi < 2; ++mi)
        #pragma unroll
        for (int ni = 0; ni < 8; ++ni)
            #pragma unroll
            for (int j = 0; j < 4; ++j) acc2[mi][ni][j] = 0.f;

    #pragma unroll 2
    for (int kk = 0; kk < 8; ++kk) {
        uint32_t a[2][4], bf[4][4];
        #pragma unroll
        for (int mi = 0; mi < 2; ++mi)
            LDSM_X4(a[mi][0], a[mi][1], a[mi][2], a[mi][3], aB2[mi] + kk * 32);
        #pragma unroll
        for (int nb = 0; nb < 4; ++nb)
            LDSM_X4(bf[nb][0], bf[nb][1], bf[nb][2], bf[nb][3], bB2[nb] + kk * 32);
        #pragma unroll
        for (int mi = 0; mi < 2; ++mi)
            #pragma unroll
            for (int ni = 0; ni < 8; ++ni)
                MMA16816(acc2[mi][ni], a[mi][0], a[mi][1], a[mi][2], a[mi][3],
                         bf[ni >> 1][(ni & 1) * 2], bf[ni >> 1][(ni & 1) * 2 + 1]);
    }

    // ---- epilogue: P tile (fp32) to global ----
    {
        int rb = m0 + (lane >> 2);
        int cb = n2 + 2 * (lane & 3);
        #pragma unroll
        for (int mi = 0; mi < 2; ++mi)
            #pragma unroll
            for (int ni = 0; ni < 8; ++ni) {
                int r = tile * M_G + rb + mi * 16;
                int c = cb + ni * 8;
                *(float2*)(g_P + (size_t)r * 256 + c) =
                    make_float2(acc2[mi][ni][0], acc2[mi][ni][1]);
                *(float2*)(g_P + (size_t)(r + 8) * 256 + c) =
                    make_float2(acc2[mi][ni][2], acc2[mi][ni][3]);
            }
    }
}

// ---------------------------------------------------------------------------
// film2: per-edge gather-add + LayerNorm + FiLM + ReLU
// grid 2048 x 256; block = 128 consecutive edges; warp = 16 edges
// ---------------------------------------------------------------------------
__global__ void __launch_bounds__(256)
film2_kernel(const int* __restrict__ eidx32, const float* __restrict__ b_film,
             float* __restrict__ out) {
    __shared__ int rowA_s[128], rowB_s[128];
    __shared__ __align__(16) float gam_s[128], bet_s[128], bf_s[128];
    int tid = threadIdx.x, wid = tid >> 5, lane = tid & 31;
    int tile = blockIdx.x;

    if (tid < 128) {
        // dtype sniff: int64 (LE) => odd words zero (values < 2^20)
        int stride = (eidx32[1] == 0 && eidx32[3] == 0 && eidx32[5] == 0) ? 2 : 1;
        int ei = eidx32[(size_t)(tile * 128 + tid) * stride];
        rowA_s[tid] = ei >> 8;
        rowB_s[tid] = ((ei >> 16) << 8) | (ei & 255);
        int batch = tile >> 7;   // position-based, matches reference reshape
        gam_s[tid] = g_gb[batch * 2 * EDGE_DIM + tid] + 1.0f;
        bet_s[tid] = g_gb[batch * 2 * EDGE_DIM + EDGE_DIM + tid];
        bf_s[tid]  = b_film[tid];
    }
    __syncthreads();

    int c4 = lane * 4;
    float4 gam4 = *(const float4*)(gam_s + c4);
    float4 bet4 = *(const float4*)(bet_s + c4);
    float4 bf4  = *(const float4*)(bf_s + c4);

    #pragma unroll 2
    for (int k = 0; k < 16; ++k) {
        int e = (wid << 4) + k;
        int rA = rowA_s[e], rB = rowB_s[e];
        float4 u = *(const float4*)(g_P + (size_t)rA * 256 + c4);
        float4 v = *(const float4*)(g_P + (size_t)rB * 256 + 128 + c4);
        float x0 = u.x + v.x + bf4.x;
        float x1 = u.y + v.y + bf4.y;
        float x2 = u.z + v.z + bf4.z;
        float x3 = u.w + v.w + bf4.w;
        float s = x0 + x1 + x2 + x3;
        float q = x0 * x0 + x1 * x1 + x2 * x2 + x3 * x3;
        #pragma unroll
        for (int o = 16; o; o >>= 1) {
            s += __shfl_xor_sync(0xffffffffu, s, o);
            q += __shfl_xor_sync(0xffffffffu, q, o);
        }
        float mu = s * (1.f / 128.f);
        float var = q * (1.f / 128.f) - mu * mu;
        float ri = rsqrtf(fmaxf(var, 0.f) + LN_EPS);
        float4 o4;
        o4.x = fmaxf((x0 - mu) * ri * gam4.x + bet4.x, 0.f);
        o4.y = fmaxf((x1 - mu) * ri * gam4.y + bet4.y, 0.f);
        o4.z = fmaxf((x2 - mu) * ri * gam4.z + bet4.z, 0.f);
        o4.w = fmaxf((x3 - mu) * ri * gam4.w + bet4.w, 0.f);
        *(float4*)(out + ((size_t)tile * 128 + e) * EDGE_DIM + c4) = o4;
    }
}

// ---------------------------------------------------------------------------
// Launch
// ---------------------------------------------------------------------------
extern "C" void kernel_launch(void* const* d_in, const int* in_sizes, int n_in,
                              void* d_out, int out_size) {
    const float* node_feats = (const float*)d_in[0];
    const float* cond_feats = (const float*)d_in[1];
    const int*   eidx       = (const int*)d_in[2];
    const float* v_node     = (const float*)d_in[3];
    const float* g_node     = (const float*)d_in[4];
    const float* b_node     = (const float*)d_in[5];
    const float* v_cond     = (const float*)d_in[6];
    const float* g_cond     = (const float*)d_in[7];
    const float* b_cond     = (const float*)d_in[8];
    const float* w_film     = (const float*)d_in[9];
    const float* b_film     = (const float*)d_in[10];
    float* out = (float*)d_out;

    cudaFuncSetAttribute(gemm_kernel, cudaFuncAttributeMaxDynamicSharedMemorySize, SMEM_GEMM);

    prep_kernel<<<384, 128>>>(v_node, g_node, w_film, v_cond, g_cond, b_cond, cond_feats);
    gemm_kernel<<<G_TILES, 256, SMEM_GEMM>>>(node_feats, b_node);
    film2_kernel<<<FILM_TILES, 256>>>(eidx, b_film, out);
}